// round 1
// baseline (speedup 1.0000x reference)
#include <cuda_runtime.h>
#include <cuda_bf16.h>
#include <mma.h>

using namespace nvcuda;

#define BATCH 16
#define L 1024
#define D 768
#define TD 2048           // padded diagonal count (actual 2047)

// -------- device scratch (allocation-free rule: __device__ globals) --------
__device__ __nv_bfloat16 g_s1n[BATCH * L * D];       // 25 MB
__device__ __nv_bfloat16 g_s2n[BATCH * L * D];       // 25 MB
__device__ float g_dskew[(size_t)BATCH * TD * L];    // 134 MB, dist skewed: (i,j)->[i+j][j]

// ---------------------------------------------------------------------------
// Kernel 1: L2-normalize rows, write bf16. One block (256 thr) per row.
// ---------------------------------------------------------------------------
__global__ void normalize_kernel(const float* __restrict__ s1,
                                 const float* __restrict__ s2) {
    int row = blockIdx.x;               // 0 .. 2*BATCH*L-1
    const float* src;
    __nv_bfloat16* dst;
    if (row < BATCH * L) {
        src = s1 + (size_t)row * D;
        dst = g_s1n + (size_t)row * D;
    } else {
        int r = row - BATCH * L;
        src = s2 + (size_t)r * D;
        dst = g_s2n + (size_t)r * D;
    }
    int t = threadIdx.x;
    float v0 = src[t];
    float v1 = src[t + 256];
    float v2 = src[t + 512];
    float ss = v0 * v0 + v1 * v1 + v2 * v2;
    #pragma unroll
    for (int o = 16; o > 0; o >>= 1)
        ss += __shfl_xor_sync(0xffffffffu, ss, o);

    __shared__ float red[8];
    __shared__ float stot;
    if ((t & 31) == 0) red[t >> 5] = ss;
    __syncthreads();
    if (t == 0) {
        float s = 0.f;
        #pragma unroll
        for (int w = 0; w < 8; w++) s += red[w];
        stot = s;
    }
    __syncthreads();
    float inv = rsqrtf(stot);   // norm ~27 >> eps, safe
    dst[t]       = __float2bfloat16(v0 * inv);
    dst[t + 256] = __float2bfloat16(v1 * inv);
    dst[t + 512] = __float2bfloat16(v2 * inv);
}

// ---------------------------------------------------------------------------
// Kernel 2: dist GEMM, bf16 wmma, fp32 accum. CTA tile 128x128, K-step 32.
// Epilogue writes dist = 1 - acc into skewed layout dskew[(i+j)][j].
// ---------------------------------------------------------------------------
#define BM 128
#define BN 128
#define BK 32
#define LDA_S 48          // padded smem row (elements), 96B rows -> 32B aligned
#define LDC_S 136         // padded fp32 epi row, 544B rows -> 32B aligned

__global__ __launch_bounds__(256) void gemm_dist_kernel() {
    extern __shared__ char smem[];
    __nv_bfloat16* As = (__nv_bfloat16*)smem;            // [128][48]
    __nv_bfloat16* Bs = As + BM * LDA_S;                  // [128][48]
    float* Cs = (float*)smem;                             // epi reuse [128][136]

    int b  = blockIdx.z;
    int m0 = blockIdx.y * BM;
    int n0 = blockIdx.x * BN;
    const __nv_bfloat16* A  = g_s1n + (size_t)b * L * D;  // [L][D] row-major
    const __nv_bfloat16* Bm = g_s2n + (size_t)b * L * D;  // [L][D]; used as B^T

    int warp = threadIdx.x >> 5;
    int wm = warp & 1;        // 2 warps in M (64 rows each)
    int wn = warp >> 1;       // 4 warps in N (32 cols each)

    wmma::fragment<wmma::accumulator, 16, 16, 16, float> acc[4][2];
    #pragma unroll
    for (int mi = 0; mi < 4; mi++)
        #pragma unroll
        for (int ni = 0; ni < 2; ni++)
            wmma::fill_fragment(acc[mi][ni], 0.0f);

    for (int k0 = 0; k0 < D; k0 += BK) {
        // stage A/B tiles: 128 rows x 32 cols bf16 each; 4 x 16B chunks per row
        #pragma unroll
        for (int i = 0; i < 2; i++) {
            int idx = threadIdx.x + i * 256;   // 0..511
            int r = idx >> 2;
            int c = (idx & 3) * 8;
            *(uint4*)&As[r * LDA_S + c] = *(const uint4*)&A [(size_t)(m0 + r) * D + k0 + c];
            *(uint4*)&Bs[r * LDA_S + c] = *(const uint4*)&Bm[(size_t)(n0 + r) * D + k0 + c];
        }
        __syncthreads();

        #pragma unroll
        for (int kk = 0; kk < BK; kk += 16) {
            wmma::fragment<wmma::matrix_a, 16, 16, 16, __nv_bfloat16, wmma::row_major> af[4];
            wmma::fragment<wmma::matrix_b, 16, 16, 16, __nv_bfloat16, wmma::col_major> bf[2];
            #pragma unroll
            for (int mi = 0; mi < 4; mi++)
                wmma::load_matrix_sync(af[mi], &As[(wm * 64 + mi * 16) * LDA_S + kk], LDA_S);
            #pragma unroll
            for (int ni = 0; ni < 2; ni++)
                wmma::load_matrix_sync(bf[ni], &Bs[(wn * 32 + ni * 16) * LDA_S + kk], LDA_S);
            #pragma unroll
            for (int mi = 0; mi < 4; mi++)
                #pragma unroll
                for (int ni = 0; ni < 2; ni++)
                    wmma::mma_sync(acc[mi][ni], af[mi], bf[ni], acc[mi][ni]);
        }
        __syncthreads();
    }

    // epilogue: stage C in smem, then skewed write dist = 1 - C
    #pragma unroll
    for (int mi = 0; mi < 4; mi++)
        #pragma unroll
        for (int ni = 0; ni < 2; ni++)
            wmma::store_matrix_sync(&Cs[(wm * 64 + mi * 16) * LDC_S + (wn * 32 + ni * 16)],
                                    acc[mi][ni], LDC_S, wmma::mem_row_major);
    __syncthreads();

    float* dst = g_dskew + (size_t)b * TD * L;
    int base_t = m0 + n0;
    // 255 tile-diagonals x 128 candidate j; writes along j are contiguous
    for (int idx = threadIdx.x; idx < 255 * 128; idx += 256) {
        int t_loc = idx >> 7;
        int j_loc = idx & 127;
        int i_loc = t_loc - j_loc;
        if (i_loc >= 0 && i_loc < 128)
            dst[(size_t)(base_t + t_loc) * L + (n0 + j_loc)] = 1.0f - Cs[i_loc * LDC_S + j_loc];
    }
}

// ---------------------------------------------------------------------------
// Kernel 3: DTW wavefront. 1 CTA per batch, thread j owns column j.
// Step t computes cell (t-j, j). Carry m = min(c_t, c_{t-1}) so only one
// value crosses each thread boundary per step. Parity double-buffered smem
// for warp boundaries -> one __syncthreads per step. dist prefetched 8 ahead.
// ---------------------------------------------------------------------------
#define PF 8
#define BIG 1e30f

__global__ __launch_bounds__(1024) void dtw_kernel(float* __restrict__ out) {
    int b = blockIdx.x;
    int j = threadIdx.x;
    int lane = j & 31;
    int warp = j >> 5;

    const float* dsk = g_dskew + (size_t)b * TD * L + j;

    __shared__ float sm[2][33];
    if (lane == 31) { sm[0][warp] = BIG; sm[1][warp] = BIG; }
    __syncthreads();

    float c_prev = BIG;
    float m = BIG;
    float result = 0.0f;

    float dbuf[PF];
    #pragma unroll
    for (int p = 0; p < PF; p++)
        dbuf[p] = dsk[(size_t)min(p, TD - 1) * L];

    // run 2048 steps (divisible by 8); step 2047 is inactive for all threads
    #pragma unroll 8
    for (int t = 0; t < 2048; t++) {
        float d = dbuf[t & (PF - 1)];
        int tn = t + PF;
        dbuf[t & (PF - 1)] = dsk[(size_t)min(tn, TD - 1) * L];

        float lm = __shfl_up_sync(0xffffffffu, m, 1);
        if (lane == 0) lm = (warp > 0) ? sm[(t & 1) ^ 1][warp - 1] : BIG;

        int i = t - j;
        float c_new = BIG;
        if (i >= 0 && i < L) {
            c_new = (t == 0) ? d : d + fminf(c_prev, lm);
            if (i == L - 1 && j == L - 1) result = c_new;
        }
        m = fminf(c_new, c_prev);
        c_prev = c_new;
        if (lane == 31) sm[t & 1][warp] = m;
        __syncthreads();
    }

    if (j == L - 1) {
        float normalized = result / (float)(2 * L);
        out[b] = 1.0f / (1.0f + normalized);
    }
}

// ---------------------------------------------------------------------------
extern "C" void kernel_launch(void* const* d_in, const int* in_sizes, int n_in,
                              void* d_out, int out_size) {
    const float* s1 = (const float*)d_in[0];
    const float* s2 = (const float*)d_in[1];
    float* out = (float*)d_out;

    cudaFuncSetAttribute(gemm_dist_kernel,
                         cudaFuncAttributeMaxDynamicSharedMemorySize, BM * LDC_S * 4);

    normalize_kernel<<<2 * BATCH * L, 256>>>(s1, s2);
    gemm_dist_kernel<<<dim3(BN == 128 ? 8 : 8, 8, BATCH), 256, BM * LDC_S * 4>>>();
    dtw_kernel<<<BATCH, 1024>>>(out);
}

// round 3
// speedup vs baseline: 1.8193x; 1.8193x over previous
#include <cuda_runtime.h>
#include <cuda_bf16.h>
#include <mma.h>
#include <cstdint>

using namespace nvcuda;

#define BATCH 16
#define L 1024
#define D 768
#define G2 768            // dsk3 group-rows per batch (max g = 511+255 = 766)
#define BIG 1e30f

// -------- device scratch (allocation-free rule: __device__ globals) --------
__device__ __nv_bfloat16 g_s1n[BATCH * L * D];                 // 25 MB
__device__ __nv_bfloat16 g_s2n[BATCH * L * D];                 // 25 MB
// dist in DTW-macro-step layout: cell (i,j) -> dsk3[b][g][r][j],
// g = i/2 + j/4, r = i&1. One group row = 2*1024 floats = 8 KB.
__device__ float g_dsk3[(size_t)BATCH * G2 * 2 * 1024];        // 100 MB

// ---------------------------------------------------------------------------
// helpers
// ---------------------------------------------------------------------------
__device__ __forceinline__ uint32_t smem_u32(const void* p) {
    uint32_t a;
    asm("{ .reg .u64 t; cvta.to.shared.u64 t, %1; cvt.u32.u64 %0, t; }"
        : "=r"(a) : "l"(p));
    return a;
}
__device__ __forceinline__ void cp16(uint32_t dst, const void* src) {
    asm volatile("cp.async.cg.shared.global [%0], [%1], 16;"
                 :: "r"(dst), "l"(src) : "memory");
}
#define CP_COMMIT() asm volatile("cp.async.commit_group;" ::: "memory")
#define CP_WAIT1()  asm volatile("cp.async.wait_group 1;" ::: "memory")

// ---------------------------------------------------------------------------
// Kernel 1: L2-normalize. One warp per row, float4 loads, shfl reduction.
// ---------------------------------------------------------------------------
__global__ __launch_bounds__(256) void normalize_kernel(const float* __restrict__ s1,
                                                        const float* __restrict__ s2) {
    int wid = threadIdx.x >> 5, lane = threadIdx.x & 31;
    int row = blockIdx.x * 8 + wid;          // 0 .. 32767
    const float* src;
    __nv_bfloat16* dst;
    if (row < BATCH * L) {
        src = s1 + (size_t)row * D;
        dst = g_s1n + (size_t)row * D;
    } else {
        int r = row - BATCH * L;
        src = s2 + (size_t)r * D;
        dst = g_s2n + (size_t)r * D;
    }
    const float4* s4 = (const float4*)src;
    float4 v[6];
    float ss = 0.f;
    #pragma unroll
    for (int i = 0; i < 6; i++) {
        v[i] = s4[lane + 32 * i];
        ss += v[i].x * v[i].x + v[i].y * v[i].y + v[i].z * v[i].z + v[i].w * v[i].w;
    }
    #pragma unroll
    for (int o = 16; o > 0; o >>= 1) ss += __shfl_xor_sync(0xffffffffu, ss, o);
    float inv = rsqrtf(ss);
    #pragma unroll
    for (int i = 0; i < 6; i++) {
        __nv_bfloat162 a = __floats2bfloat162_rn(v[i].x * inv, v[i].y * inv);
        __nv_bfloat162 b = __floats2bfloat162_rn(v[i].z * inv, v[i].w * inv);
        uint2 pk;
        pk.x = *(const uint32_t*)&a;
        pk.y = *(const uint32_t*)&b;
        ((uint2*)dst)[lane + 32 * i] = pk;
    }
}

// ---------------------------------------------------------------------------
// Kernel 2: wmma bf16 GEMM, cp.async 3-stage pipeline. CTA 128x128, BK=32,
// 8 warps (2x4), warp tile 64x32. Epilogue: acc -> smem -> skewed write of
// dist = 1 - dot into dsk3 layout.
// ---------------------------------------------------------------------------
#define BM 128
#define BN 128
#define BK 32
#define STAGES 3
#define NITER (D / BK)    // 24
#define LDA_S 48          // padded bf16 smem row
#define LDC_S 136         // padded fp32 epi row
#define STAGE_ELEMS (BM * LDA_S)              // per matrix per stage (bf16)
#define STAGE_BYTES (2 * STAGE_ELEMS * 2)     // A+B per stage = 24576 B
#define SMEM_BYTES (STAGES * STAGE_BYTES)     // 73728 B  (>= 128*136*4 epi)

__global__ __launch_bounds__(256) void gemm_dist_kernel() {
    extern __shared__ char smem[];
    __nv_bfloat16* sA[STAGES];
    __nv_bfloat16* sB[STAGES];
    #pragma unroll
    for (int s = 0; s < STAGES; s++) {
        sA[s] = (__nv_bfloat16*)(smem + s * STAGE_BYTES);
        sB[s] = sA[s] + STAGE_ELEMS;
    }

    int tid = threadIdx.x;
    int b  = blockIdx.z;
    int m0 = blockIdx.y * BM;
    int n0 = blockIdx.x * BN;
    const __nv_bfloat16* A  = g_s1n + (size_t)b * L * D;
    const __nv_bfloat16* Bm = g_s2n + (size_t)b * L * D;

    int warp = tid >> 5;
    int wm = warp & 1;        // 2 warps in M (64 rows)
    int wn = warp >> 1;       // 4 warps in N (32 cols)

    // load indices: 512 16B chunks per matrix per stage; 2 per thread
    int r0 = tid >> 2;                 // chunk set 0 row
    int c0 = (tid & 3) * 8;
    int r1 = (tid + 256) >> 2;
    int c1 = c0;                       // (idx&3) identical for +256

    wmma::fragment<wmma::accumulator, 16, 16, 16, float> acc[4][2];
    #pragma unroll
    for (int mi = 0; mi < 4; mi++)
        #pragma unroll
        for (int ni = 0; ni < 2; ni++)
            wmma::fill_fragment(acc[mi][ni], 0.0f);

    // prologue: stage 0, 1
    #pragma unroll
    for (int s = 0; s < 2; s++) {
        int k0 = s * BK;
        cp16(smem_u32(&sA[s][r0 * LDA_S + c0]), A  + (size_t)(m0 + r0) * D + k0 + c0);
        cp16(smem_u32(&sA[s][r1 * LDA_S + c1]), A  + (size_t)(m0 + r1) * D + k0 + c1);
        cp16(smem_u32(&sB[s][r0 * LDA_S + c0]), Bm + (size_t)(n0 + r0) * D + k0 + c0);
        cp16(smem_u32(&sB[s][r1 * LDA_S + c1]), Bm + (size_t)(n0 + r1) * D + k0 + c1);
        CP_COMMIT();
    }

    for (int c = 0; c < NITER; c++) {
        CP_WAIT1();
        __syncthreads();
        int st = c % STAGES;

        #pragma unroll
        for (int kk = 0; kk < BK; kk += 16) {
            wmma::fragment<wmma::matrix_a, 16, 16, 16, __nv_bfloat16, wmma::row_major> af[4];
            wmma::fragment<wmma::matrix_b, 16, 16, 16, __nv_bfloat16, wmma::col_major> bf[2];
            #pragma unroll
            for (int mi = 0; mi < 4; mi++)
                wmma::load_matrix_sync(af[mi], &sA[st][(wm * 64 + mi * 16) * LDA_S + kk], LDA_S);
            #pragma unroll
            for (int ni = 0; ni < 2; ni++)
                wmma::load_matrix_sync(bf[ni], &sB[st][(wn * 32 + ni * 16) * LDA_S + kk], LDA_S);
            #pragma unroll
            for (int mi = 0; mi < 4; mi++)
                #pragma unroll
                for (int ni = 0; ni < 2; ni++)
                    wmma::mma_sync(acc[mi][ni], af[mi], bf[ni], acc[mi][ni]);
        }

        if (c + 2 < NITER) {
            int sn = (c + 2) % STAGES;
            int k0 = (c + 2) * BK;
            cp16(smem_u32(&sA[sn][r0 * LDA_S + c0]), A  + (size_t)(m0 + r0) * D + k0 + c0);
            cp16(smem_u32(&sA[sn][r1 * LDA_S + c1]), A  + (size_t)(m0 + r1) * D + k0 + c1);
            cp16(smem_u32(&sB[sn][r0 * LDA_S + c0]), Bm + (size_t)(n0 + r0) * D + k0 + c0);
            cp16(smem_u32(&sB[sn][r1 * LDA_S + c1]), Bm + (size_t)(n0 + r1) * D + k0 + c1);
        }
        CP_COMMIT();
    }

    // epilogue: stage acc into smem (reuse), then skewed write 1 - v
    __syncthreads();
    float* Cs = (float*)smem;
    #pragma unroll
    for (int mi = 0; mi < 4; mi++)
        #pragma unroll
        for (int ni = 0; ni < 2; ni++)
            wmma::store_matrix_sync(&Cs[(wm * 64 + mi * 16) * LDC_S + (wn * 32 + ni * 16)],
                                    acc[mi][ni], LDC_S, wmma::mem_row_major);
    __syncthreads();

    // cell (il,jl): group row gl = il/2 + jl/4, subrow rr = il&1
    float* dst = g_dsk3 + ((size_t)b * G2 + (m0 >> 1) + (n0 >> 2)) * 2048;
    int jl = tid & 127;
    int rr = tid >> 7;
    #pragma unroll 5
    for (int gl = 0; gl < 95; gl++) {
        int il = 2 * (gl - (jl >> 2)) + rr;
        if ((unsigned)il < 128u)
            dst[(size_t)gl * 2048 + rr * 1024 + n0 + jl] = 1.0f - Cs[il * LDC_S + jl];
    }
}

// ---------------------------------------------------------------------------
// Kernel 3: DTW wavefront. 256 threads, thread jg owns cols [4jg,4jg+4),
// 2 rows per macro-step, 767 active steps (run 768). Neighbor handoff:
// 2 floats via shfl (+ parity double-buffered smem at warp boundaries),
// one __syncthreads per step. dist rows prefetched 8 steps ahead.
// ---------------------------------------------------------------------------
#define PF 8

__global__ __launch_bounds__(256) void dtw_kernel(float* __restrict__ out) {
    int b = blockIdx.x;
    int jg = threadIdx.x, lane = jg & 31, w = jg >> 5;

    const float4* base = (const float4*)(g_dsk3 + (size_t)b * G2 * 2048) + jg;
    // group row g, subrow r: float4 index g*512 + r*256 (+jg folded into base)

    __shared__ float pub[2][8][2];
    if (lane < 2) { pub[0][w][lane] = BIG; pub[1][w][lane] = BIG; }
    __syncthreads();

    float p0 = BIG, p1 = BIG, p2 = BIG, p3 = BIG;   // row i0-1 of own 4 cols
    float c3r0 = BIG, c3r1 = BIG, prev_vb = BIG;
    float res = 0.0f;

    float4 ring0[PF], ring1[PF];
    #pragma unroll
    for (int s = 0; s < PF; s++) {
        int g = min(s, G2 - 1);
        ring0[s] = base[g * 512];
        ring1[s] = base[g * 512 + 256];
    }

    #pragma unroll 8
    for (int S = 0; S < 768; S++) {
        float4 da = ring0[S & (PF - 1)];
        float4 db = ring1[S & (PF - 1)];
        int gn = min(S + PF, G2 - 1);
        ring0[S & (PF - 1)] = base[gn * 512];
        ring1[S & (PF - 1)] = base[gn * 512 + 256];

        float va = __shfl_up_sync(0xffffffffu, c3r0, 1);  // dtw[i0][4jg-1]
        float vb = __shfl_up_sync(0xffffffffu, c3r1, 1);  // dtw[i0+1][4jg-1]
        if (lane == 0) {
            if (w > 0) {
                va = pub[(S & 1) ^ 1][w - 1][0];
                vb = pub[(S & 1) ^ 1][w - 1][1];
            } else { va = BIG; vb = BIG; }
        }

        int i0 = 2 * (S - jg);
        if ((unsigned)i0 < 1024u) {
            // row i0:  needs dtw[i0-1][4jg-1] = prev_vb
            float e0 = fminf(prev_vb, p0);
            float e1 = fminf(p0, p1), e2 = fminf(p1, p2), e3 = fminf(p2, p3);
            float c0 = da.x + fminf(va, e0);
            if (i0 == 0 && jg == 0) c0 = da.x;
            float c1 = da.y + fminf(c0, e1);
            float c2 = da.z + fminf(c1, e2);
            float c3 = da.w + fminf(c2, e3);
            // row i0+1
            float f0 = fminf(va, c0);
            float g0 = db.x + fminf(vb, f0);
            float g1 = db.y + fminf(g0, fminf(c0, c1));
            float g2 = db.z + fminf(g1, fminf(c1, c2));
            float g3 = db.w + fminf(g2, fminf(c2, c3));
            p0 = g0; p1 = g1; p2 = g2; p3 = g3;
            c3r0 = c3; c3r1 = g3;
            if (i0 == 1022 && jg == 255) res = g3;
        }
        prev_vb = vb;
        if (lane == 31) { pub[S & 1][w][0] = c3r0; pub[S & 1][w][1] = c3r1; }
        __syncthreads();
    }

    if (jg == 255)
        out[b] = 1.0f / (1.0f + res * (1.0f / 2048.0f));
}

// ---------------------------------------------------------------------------
extern "C" void kernel_launch(void* const* d_in, const int* in_sizes, int n_in,
                              void* d_out, int out_size) {
    const float* s1 = (const float*)d_in[0];
    const float* s2 = (const float*)d_in[1];
    float* out = (float*)d_out;

    cudaFuncSetAttribute(gemm_dist_kernel,
                         cudaFuncAttributeMaxDynamicSharedMemorySize, SMEM_BYTES);

    normalize_kernel<<<4096, 256>>>(s1, s2);
    gemm_dist_kernel<<<dim3(L / BN, L / BM, BATCH), 256, SMEM_BYTES>>>();
    dtw_kernel<<<BATCH, 256>>>(out);
}